// round 13
// baseline (speedup 1.0000x reference)
#include <cuda_runtime.h>
#include <cstdint>

#define N_TOKENS (16*8192)
#define HD       256
#define NEXP     32
#define BATCH    16
#define SEQ      8192
#define TPB      256
#define WARPS    8
#define TOK_PER_TILE 32
#define NTILES   (N_TOKENS/TOK_PER_TILE)   // 4096 warp-tiles
#define NBLK     296                       // 2 x 148 SMs
#define NH       (HD/16)                   // 16 h-groups (16 k each)
// B fragment table: [ks 32][nt 4][lane 32] x uint4 {bh_r0, bh_r1, bl_r0, bl_r1} = 64 KB
#define SMEM_DYN (32*4*32*4*4)

__device__ float g_ssum[BATCH*NEXP];
__device__ int   g_cnt [BATCH*NEXP];
__device__ unsigned g_done;

__device__ __forceinline__ uint32_t tf32_hi(float x) {
    uint32_t r; asm("cvt.rna.tf32.f32 %0, %1;" : "=r"(r) : "f"(x)); return r;
}
__device__ __forceinline__ void mma_tf32(float* c,
        uint32_t a0, uint32_t a1, uint32_t a2, uint32_t a3,
        uint32_t b0, uint32_t b1) {
    asm volatile(
        "mma.sync.aligned.m16n8k8.row.col.f32.tf32.tf32.f32 "
        "{%0,%1,%2,%3}, {%4,%5,%6,%7}, {%8,%9}, {%0,%1,%2,%3};"
        : "+f"(c[0]), "+f"(c[1]), "+f"(c[2]), "+f"(c[3])
        : "r"(a0), "r"(a1), "r"(a2), "r"(a3), "r"(b0), "r"(b1));
}

extern __shared__ uint32_t Btab[];

__global__ void __launch_bounds__(TPB, 2)
gate_kernel(const float* __restrict__ hs, const float* __restrict__ w,
            float* __restrict__ out)
{
    __shared__ float s_aux[2][NEXP];
    __shared__ int   s_cnt[2][NEXP];
    __shared__ int   s_last;

    const int tid  = threadIdx.x;
    const int lane = tid & 31;
    const int warp = tid >> 5;
    const int lq   = lane & 3;
    const int lr   = lane >> 2;

    const int t_start = (int)(((long long)blockIdx.x * NTILES) / NBLK);
    const int t_end   = (int)(((long long)(blockIdx.x + 1) * NTILES) / NBLK);
    const int b_base  = t_start >> 8;

    // ---- build B fragment table (hi/lo tf32, float4-era k-permutation) ----
    #pragma unroll 4
    for (int it = 0; it < NEXP; it++) {
        float v = w[it*HD + tid];
        uint32_t hi = tf32_hi(v);
        float lo = v - __uint_as_float(hi);
        int k = tid;
        int h = k >> 4, j = k & 15, q = j >> 2, rr = j & 3;
        int ks = 2*h + (rr >> 1), r = rr & 1;
        int nt = it >> 3, t = (it & 7)*4 + q;
        int idx = ((ks*4 + nt)*32 + t)*4;
        Btab[idx + r]     = hi;
        Btab[idx + 2 + r] = __float_as_uint(lo);
    }
    if (tid < 2*NEXP) { s_aux[tid>>5][tid&31] = 0.0f; s_cnt[tid>>5][tid&31] = 0; }
    __syncthreads();

    for (int tile = t_start + warp; tile < t_end; tile += WARPS) {
        const int tb = tile * TOK_PER_TILE;
        const int bi = (tile >> 8) - b_base;
        const float4* rp[4];
        #pragma unroll
        for (int i = 0; i < 4; i++)
            rp[i] = (const float4*)(hs + (size_t)(tb + i*8 + lr)*HD);

        float acc[2][4][4];
        #pragma unroll
        for (int mt = 0; mt < 2; mt++)
            #pragma unroll
            for (int nt = 0; nt < 4; nt++)
                #pragma unroll
                for (int i = 0; i < 4; i++) acc[mt][nt][i] = 0.0f;

        float4 cur[4], nxt[4];
        #pragma unroll
        for (int i = 0; i < 4; i++) cur[i] = rp[i][lq];

        #pragma unroll 2
        for (int h = 0; h < NH; h++) {
            if (h + 1 < NH) {                 // distance-1 prefetch (in flight over MMAs)
                #pragma unroll
                for (int i = 0; i < 4; i++) nxt[i] = rp[i][(h+1)*4 + lq];
            }
            #pragma unroll
            for (int s01 = 0; s01 < 2; s01++) {
                uint32_t ah[4][2], al[4][2];
                #pragma unroll
                for (int i = 0; i < 4; i++) {
                    float f0 = s01 ? cur[i].z : cur[i].x;
                    float f1 = s01 ? cur[i].w : cur[i].y;
                    ah[i][0] = tf32_hi(f0);
                    ah[i][1] = tf32_hi(f1);
                    al[i][0] = __float_as_uint(f0 - __uint_as_float(ah[i][0]));
                    al[i][1] = __float_as_uint(f1 - __uint_as_float(ah[i][1]));
                }
                const uint32_t* bt = &Btab[((8*h + s01*4)*32 + lane)*4];
                uint4 bb[4];
                #pragma unroll
                for (int nt = 0; nt < 4; nt++) bb[nt] = *(const uint4*)(bt + nt*128);

                // 3 passes over 8 independent accumulators:
                // same-acc reuse distance = 8 MMA issues (covers HMMA RAW latency)
                #pragma unroll
                for (int nt = 0; nt < 4; nt++)
                    #pragma unroll
                    for (int mt = 0; mt < 2; mt++)
                        mma_tf32(acc[mt][nt], ah[mt*2][0], ah[mt*2+1][0],
                                 ah[mt*2][1], ah[mt*2+1][1], bb[nt].x, bb[nt].y);
                #pragma unroll
                for (int nt = 0; nt < 4; nt++)
                    #pragma unroll
                    for (int mt = 0; mt < 2; mt++)
                        mma_tf32(acc[mt][nt], ah[mt*2][0], ah[mt*2+1][0],
                                 ah[mt*2][1], ah[mt*2+1][1], bb[nt].z, bb[nt].w);
                #pragma unroll
                for (int nt = 0; nt < 4; nt++)
                    #pragma unroll
                    for (int mt = 0; mt < 2; mt++)
                        mma_tf32(acc[mt][nt], al[mt*2][0], al[mt*2+1][0],
                                 al[mt*2][1], al[mt*2+1][1], bb[nt].x, bb[nt].y);
            }
            #pragma unroll
            for (int i = 0; i < 4; i++) cur[i] = nxt[i];
        }

        // ---- epilogue: token row (mt*16 + half*8 + lr), logits across quad ----
        float aux8[8];
        #pragma unroll
        for (int i = 0; i < 8; i++) aux8[i] = 0.0f;

        #pragma unroll
        for (int mt = 0; mt < 2; mt++) {
            #pragma unroll
            for (int half = 0; half < 2; half++) {
                float lg[8];
                #pragma unroll
                for (int nt = 0; nt < 4; nt++) {
                    lg[nt*2]   = acc[mt][nt][half*2];
                    lg[nt*2+1] = acc[mt][nt][half*2+1];
                }
                float m = lg[0]; int a = lq*2;
                #pragma unroll
                for (int i = 1; i < 8; i++) {
                    int e = (i>>1)*8 + lq*2 + (i&1);
                    if (lg[i] > m) { m = lg[i]; a = e; }
                }
                #pragma unroll
                for (int d = 1; d <= 2; d <<= 1) {
                    float om = __shfl_xor_sync(0xffffffffu, m, d);
                    int   oa = __shfl_xor_sync(0xffffffffu, a, d);
                    if (om > m || (om == m && oa < a)) { m = om; a = oa; }
                }
                float ex[8]; float s = 0.0f;
                #pragma unroll
                for (int i = 0; i < 8; i++) { ex[i] = __expf(lg[i] - m); s += ex[i]; }
                #pragma unroll
                for (int d = 1; d <= 2; d <<= 1) s += __shfl_xor_sync(0xffffffffu, s, d);
                float inv = 1.0f / s;
                #pragma unroll
                for (int i = 0; i < 8; i++) aux8[i] += ex[i] * inv;
                if (lq == 0) {
                    int gidx = tb + mt*16 + half*8 + lr;
                    out[gidx]            = (float)a;
                    out[N_TOKENS + gidx] = inv;
                    atomicAdd(&s_cnt[bi][a], 1);
                }
            }
        }

        #pragma unroll
        for (int i = 0; i < 8; i++) {
            float v = aux8[i];
            #pragma unroll
            for (int d = 4; d <= 16; d <<= 1) v += __shfl_xor_sync(0xffffffffu, v, d);
            if (lane < 4) atomicAdd(&s_aux[bi][(i>>1)*8 + lane*2 + (i&1)], v);
        }
    }
    __syncthreads();

    if (tid < 2*NEXP) {
        int r = tid >> 5, e = tid & 31;
        int br = b_base + r;
        if (br < BATCH) {
            atomicAdd(&g_ssum[br*NEXP + e], s_aux[r][e]);
            atomicAdd(&g_cnt [br*NEXP + e], s_cnt[r][e]);
        }
    }

    // ---- last block: finalize aux loss, reset globals ----
    if (tid == 0) {
        __threadfence();
        unsigned ticket = atomicAdd(&g_done, 1u);
        s_last = (ticket == (unsigned)(gridDim.x - 1));
    }
    __syncthreads();
    if (s_last) {
        __threadfence();
        __shared__ float red[TPB];
        float term = 0.0f;
        #pragma unroll
        for (int i = tid; i < BATCH*NEXP; i += TPB)
            term += ((float)g_cnt[i] * (1.0f/256.0f)) * (g_ssum[i] * (1.0f/(float)SEQ));
        red[tid] = term;
        __syncthreads();
        #pragma unroll
        for (int s2 = TPB/2; s2 > 0; s2 >>= 1) {
            if (tid < s2) red[tid] += red[tid + s2];
            __syncthreads();
        }
        if (tid == 0) out[2*N_TOKENS] = red[0] * (0.001f / (float)BATCH);
        #pragma unroll
        for (int i = tid; i < BATCH*NEXP; i += TPB) { g_ssum[i] = 0.0f; g_cnt[i] = 0; }
        if (tid == 0) g_done = 0u;
    }
}

extern "C" void kernel_launch(void* const* d_in, const int* in_sizes, int n_in,
                              void* d_out, int out_size) {
    const float* hs = (const float*)d_in[0];
    const float* w  = (const float*)d_in[1];
    float* out = (float*)d_out;
    cudaFuncSetAttribute(gate_kernel, cudaFuncAttributeMaxDynamicSharedMemorySize, SMEM_DYN);
    gate_kernel<<<NBLK, TPB, SMEM_DYN>>>(hs, w, out);
}

// round 15
// speedup vs baseline: 1.4678x; 1.4678x over previous
#include <cuda_runtime.h>
#include <cstdint>

#define N_TOKENS (16*8192)
#define HD       256
#define NEXP     32
#define BATCH    16
#define SEQ      8192
#define TPB      256
#define WARPS    8
#define TOK_PER_TILE 32
#define NTILES   (N_TOKENS/TOK_PER_TILE)   // 4096 warp-tiles
#define NBLK     296                       // 2 x 148 SMs
#define NH       (HD/16)                   // 16 h-groups (16 k each)
#define NSTAGE   2
#define STAGE_B  2048                      // 32 rows x 16 floats
// dyn smem: B table 64 KB + A rings 8*2*2 KB = 96 KB -> 2 blocks/SM
#define BT_BYTES (32*4*32*4*4)
#define SMEM_DYN (BT_BYTES + WARPS*NSTAGE*STAGE_B)

__device__ float g_ssum[BATCH*NEXP];
__device__ int   g_cnt [BATCH*NEXP];
__device__ unsigned g_done;

__device__ __forceinline__ uint32_t tf32_hi(float x) {
    uint32_t r; asm("cvt.rna.tf32.f32 %0, %1;" : "=r"(r) : "f"(x)); return r;
}
__device__ __forceinline__ void mma_tf32(float* c,
        uint32_t a0, uint32_t a1, uint32_t a2, uint32_t a3,
        uint32_t b0, uint32_t b1) {
    asm volatile(
        "mma.sync.aligned.m16n8k8.row.col.f32.tf32.tf32.f32 "
        "{%0,%1,%2,%3}, {%4,%5,%6,%7}, {%8,%9}, {%0,%1,%2,%3};"
        : "+f"(c[0]), "+f"(c[1]), "+f"(c[2]), "+f"(c[3])
        : "r"(a0), "r"(a1), "r"(a2), "r"(a3), "r"(b0), "r"(b1));
}
__device__ __forceinline__ void cp_async16(uint32_t dst, const void* src) {
    asm volatile("cp.async.cg.shared.global [%0], [%1], 16;\n" :: "r"(dst), "l"(src));
}
__device__ __forceinline__ void cp_commit() {
    asm volatile("cp.async.commit_group;\n");
}
template<int N> __device__ __forceinline__ void cp_wait() {
    asm volatile("cp.async.wait_group %0;\n" :: "n"(N));
}

extern __shared__ uint32_t smem_dyn[];

__global__ void __launch_bounds__(TPB, 2)
gate_kernel(const float* __restrict__ hs, const float* __restrict__ w,
            float* __restrict__ out)
{
    __shared__ float s_aux[2][NEXP];
    __shared__ int   s_cnt[2][NEXP];
    __shared__ int   s_last;

    uint32_t* Btab = smem_dyn;
    char* Aring = (char*)smem_dyn + BT_BYTES;

    const int tid  = threadIdx.x;
    const int lane = tid & 31;
    const int warp = tid >> 5;
    const int lq   = lane & 3;
    const int lr   = lane >> 2;

    const int t_start = (int)(((long long)blockIdx.x * NTILES) / NBLK);
    const int t_end   = (int)(((long long)(blockIdx.x + 1) * NTILES) / NBLK);
    const int b_base  = t_start >> 8;

    // ---- build B fragment table (hi/lo tf32; same permutation as R11) ----
    #pragma unroll 4
    for (int it = 0; it < NEXP; it++) {
        float v = w[it*HD + tid];
        uint32_t hi = tf32_hi(v);
        float lo = v - __uint_as_float(hi);
        int k = tid;
        int h = k >> 4, j = k & 15, q = j >> 2, rr = j & 3;
        int ks = 2*h + (rr >> 1), r = rr & 1;
        int nt = it >> 3, t = (it & 7)*4 + q;
        int idx = ((ks*4 + nt)*32 + t)*4;
        Btab[idx + r]     = hi;
        Btab[idx + 2 + r] = __float_as_uint(lo);
    }
    if (tid < 2*NEXP) { s_aux[tid>>5][tid&31] = 0.0f; s_cnt[tid>>5][tid&31] = 0; }
    __syncthreads();

    // this warp's A ring (2 stages x 2 KB); lane's cp.async row/granule
    char* Awarp = Aring + warp * (NSTAGE*STAGE_B);
    const uint32_t Abase = (uint32_t)__cvta_generic_to_shared(Awarp);
    const int cp_row = lane >> 2;        // 0..7 (x4 iterations -> 32 rows)
    const int cp_gr  = lane & 3;         // 16B granule within 64B row

    for (int tile = t_start + warp; tile < t_end; tile += WARPS) {
        const int tb = tile * TOK_PER_TILE;
        const int bi = (tile >> 8) - b_base;
        const float* xbase = hs + (size_t)tb * HD;

        // ---- prologue: stage h-groups 0 and 1 ----
        #pragma unroll
        for (int p = 0; p < NSTAGE; p++) {
            uint32_t dst = Abase + p*STAGE_B;
            #pragma unroll
            for (int it = 0; it < 4; it++) {
                int row = it*8 + cp_row;
                cp_async16(dst + row*64 + cp_gr*16,
                           xbase + (size_t)row*HD + p*16 + cp_gr*4);
            }
            cp_commit();
        }

        float acc[2][4][4];
        #pragma unroll
        for (int mt = 0; mt < 2; mt++)
            #pragma unroll
            for (int nt = 0; nt < 4; nt++)
                #pragma unroll
                for (int i = 0; i < 4; i++) acc[mt][nt][i] = 0.0f;

        #pragma unroll
        for (int h = 0; h < NH; h++) {
            cp_wait<1>();                            // stage h resident (issued 2 iters ago)
            const char* st = Awarp + (h & 1)*STAGE_B;

            // fragment rows from smem: addr = lane*16 within 512B -> conflict-free
            float4 cur[4];
            #pragma unroll
            for (int i = 0; i < 4; i++)
                cur[i] = *(const float4*)(st + (i*8 + lr)*64 + lq*16);

            // refill this slot with h-group h+2
            if (h + NSTAGE < NH) {
                uint32_t dst = Abase + (h & 1)*STAGE_B;
                #pragma unroll
                for (int it = 0; it < 4; it++) {
                    int row = it*8 + cp_row;
                    cp_async16(dst + row*64 + cp_gr*16,
                               xbase + (size_t)row*HD + (h+NSTAGE)*16 + cp_gr*4);
                }
            }
            cp_commit();                             // one group per iteration (may be empty)

            #pragma unroll
            for (int s01 = 0; s01 < 2; s01++) {
                uint32_t ah[4][2], al[4][2];
                #pragma unroll
                for (int i = 0; i < 4; i++) {
                    float f0 = s01 ? cur[i].z : cur[i].x;
                    float f1 = s01 ? cur[i].w : cur[i].y;
                    ah[i][0] = tf32_hi(f0);
                    ah[i][1] = tf32_hi(f1);
                    al[i][0] = __float_as_uint(f0 - __uint_as_float(ah[i][0]));
                    al[i][1] = __float_as_uint(f1 - __uint_as_float(ah[i][1]));
                }
                const uint32_t* bt = &Btab[((8*h + s01*4)*32 + lane)*4];
                #pragma unroll
                for (int nt = 0; nt < 4; nt++) {
                    uint4 bb = *(const uint4*)(bt + nt*128);
                    #pragma unroll
                    for (int mt = 0; mt < 2; mt++) {
                        const int r0 = mt*2, r1 = mt*2 + 1;
                        mma_tf32(acc[mt][nt], ah[r0][0], ah[r1][0], ah[r0][1], ah[r1][1], bb.x, bb.y);
                        mma_tf32(acc[mt][nt], ah[r0][0], ah[r1][0], ah[r0][1], ah[r1][1], bb.z, bb.w);
                        mma_tf32(acc[mt][nt], al[r0][0], al[r1][0], al[r0][1], al[r1][1], bb.x, bb.y);
                    }
                }
            }
        }
        cp_wait<0>();                                // drain before ring reuse next tile

        // ---- epilogue: token row (mt*16 + half*8 + lr), logits across quad ----
        float aux8[8];
        #pragma unroll
        for (int i = 0; i < 8; i++) aux8[i] = 0.0f;

        #pragma unroll
        for (int mt = 0; mt < 2; mt++) {
            #pragma unroll
            for (int half = 0; half < 2; half++) {
                float lg[8];
                #pragma unroll
                for (int nt = 0; nt < 4; nt++) {
                    lg[nt*2]   = acc[mt][nt][half*2];
                    lg[nt*2+1] = acc[mt][nt][half*2+1];
                }
                float m = lg[0]; int a = lq*2;
                #pragma unroll
                for (int i = 1; i < 8; i++) {
                    int e = (i>>1)*8 + lq*2 + (i&1);
                    if (lg[i] > m) { m = lg[i]; a = e; }
                }
                #pragma unroll
                for (int d = 1; d <= 2; d <<= 1) {
                    float om = __shfl_xor_sync(0xffffffffu, m, d);
                    int   oa = __shfl_xor_sync(0xffffffffu, a, d);
                    if (om > m || (om == m && oa < a)) { m = om; a = oa; }
                }
                float ex[8]; float s = 0.0f;
                #pragma unroll
                for (int i = 0; i < 8; i++) { ex[i] = __expf(lg[i] - m); s += ex[i]; }
                #pragma unroll
                for (int d = 1; d <= 2; d <<= 1) s += __shfl_xor_sync(0xffffffffu, s, d);
                float inv = 1.0f / s;
                #pragma unroll
                for (int i = 0; i < 8; i++) aux8[i] += ex[i] * inv;
                if (lq == 0) {
                    int gidx = tb + mt*16 + half*8 + lr;
                    out[gidx]            = (float)a;
                    out[N_TOKENS + gidx] = inv;
                    atomicAdd(&s_cnt[bi][a], 1);
                }
            }
        }

        #pragma unroll
        for (int i = 0; i < 8; i++) {
            float v = aux8[i];
            #pragma unroll
            for (int d = 4; d <= 16; d <<= 1) v += __shfl_xor_sync(0xffffffffu, v, d);
            if (lane < 4) atomicAdd(&s_aux[bi][(i>>1)*8 + lane*2 + (i&1)], v);
        }
    }
    __syncthreads();

    if (tid < 2*NEXP) {
        int r = tid >> 5, e = tid & 31;
        int br = b_base + r;
        if (br < BATCH) {
            atomicAdd(&g_ssum[br*NEXP + e], s_aux[r][e]);
            atomicAdd(&g_cnt [br*NEXP + e], s_cnt[r][e]);
        }
    }

    // ---- last block: finalize aux loss, reset globals ----
    if (tid == 0) {
        __threadfence();
        unsigned ticket = atomicAdd(&g_done, 1u);
        s_last = (ticket == (unsigned)(gridDim.x - 1));
    }
    __syncthreads();
    if (s_last) {
        __threadfence();
        __shared__ float red[TPB];
        float term = 0.0f;
        #pragma unroll
        for (int i = tid; i < BATCH*NEXP; i += TPB)
            term += ((float)g_cnt[i] * (1.0f/256.0f)) * (g_ssum[i] * (1.0f/(float)SEQ));
        red[tid] = term;
        __syncthreads();
        #pragma unroll
        for (int s2 = TPB/2; s2 > 0; s2 >>= 1) {
            if (tid < s2) red[tid] += red[tid + s2];
            __syncthreads();
        }
        if (tid == 0) out[2*N_TOKENS] = red[0] * (0.001f / (float)BATCH);
        #pragma unroll
        for (int i = tid; i < BATCH*NEXP; i += TPB) { g_ssum[i] = 0.0f; g_cnt[i] = 0; }
        if (tid == 0) g_done = 0u;
    }
}

extern "C" void kernel_launch(void* const* d_in, const int* in_sizes, int n_in,
                              void* d_out, int out_size) {
    const float* hs = (const float*)d_in[0];
    const float* w  = (const float*)d_in[1];
    float* out = (float*)d_out;
    cudaFuncSetAttribute(gate_kernel, cudaFuncAttributeMaxDynamicSharedMemorySize, SMEM_DYN);
    gate_kernel<<<NBLK, TPB, SMEM_DYN>>>(hs, w, out);
}

// round 17
// speedup vs baseline: 1.6761x; 1.1419x over previous
#include <cuda_runtime.h>
#include <cuda_fp16.h>
#include <cstdint>

#define N_TOKENS (16*8192)
#define HD       256
#define NEXP     32
#define BATCH    16
#define SEQ      8192
#define TPB      256
#define WARPS    8
#define TOK_PER_TILE 32
#define NTILES   (N_TOKENS/TOK_PER_TILE)   // 4096 warp-tiles
#define NBLK     296                       // 2 x 148 SMs
#define NH       (HD/16)                   // 16 h-groups = one k16 step each
#define NSTAGE   2
#define STAGE_B  2048                      // 32 rows x 16 floats
// B table: [h 16][nt 4][lane 32] x uint4 {bh0,bh1,bm0,bm1} (f16x2 each) = 32 KB
#define BT_BYTES (16*4*32*16)
#define SMEM_DYN (BT_BYTES + WARPS*NSTAGE*STAGE_B)   // 32K + 32K = 64K

__device__ float g_ssum[BATCH*NEXP];
__device__ int   g_cnt [BATCH*NEXP];
__device__ unsigned g_done;

__device__ __forceinline__ uint32_t pk16(float lo, float hi) {
    uint32_t r; asm("cvt.rn.f16x2.f32 %0, %1, %2;" : "=r"(r) : "f"(hi), "f"(lo)); return r;
}
__device__ __forceinline__ void mma_f16(float* c,
        uint32_t a0, uint32_t a1, uint32_t a2, uint32_t a3,
        uint32_t b0, uint32_t b1) {
    asm volatile(
        "mma.sync.aligned.m16n8k16.row.col.f32.f16.f16.f32 "
        "{%0,%1,%2,%3}, {%4,%5,%6,%7}, {%8,%9}, {%0,%1,%2,%3};"
        : "+f"(c[0]), "+f"(c[1]), "+f"(c[2]), "+f"(c[3])
        : "r"(a0), "r"(a1), "r"(a2), "r"(a3), "r"(b0), "r"(b1));
}
__device__ __forceinline__ void cp_async16(uint32_t dst, const void* src) {
    asm volatile("cp.async.cg.shared.global [%0], [%1], 16;\n" :: "r"(dst), "l"(src));
}
__device__ __forceinline__ void cp_commit() {
    asm volatile("cp.async.commit_group;\n");
}
template<int N> __device__ __forceinline__ void cp_wait() {
    asm volatile("cp.async.wait_group %0;\n" :: "n"(N));
}

extern __shared__ uint32_t smem_dyn[];

__global__ void __launch_bounds__(TPB, 2)
gate_kernel(const float* __restrict__ hs, const float* __restrict__ w,
            float* __restrict__ out)
{
    __shared__ float s_aux[2][NEXP];
    __shared__ int   s_cnt[2][NEXP];
    __shared__ int   s_last;

    uint32_t* Btab = smem_dyn;
    char* Aring = (char*)smem_dyn + BT_BYTES;

    const int tid  = threadIdx.x;
    const int lane = tid & 31;
    const int warp = tid >> 5;
    const int lq   = lane & 3;     // k-quad (frag col group) / C col group
    const int lr   = lane >> 2;    // frag row (0..7)

    const int t_start = (int)(((long long)blockIdx.x * NTILES) / NBLK);
    const int t_end   = (int)(((long long)(blockIdx.x + 1) * NTILES) / NBLK);
    const int b_base  = t_start >> 8;

    // ---- build B fragment table: exact hi/lo split, lo pre-scaled x1024 ----
    // physical k=tid: h=k>>4, j=k&15, c=j>>2, p=j&3 maps to logical frag slot:
    // p=0,1 -> b0 halves (logical 2c,2c+1); p=2,3 -> b1 halves (2c+8,2c+9)
    {
        __half* Bt = (__half*)Btab;
        #pragma unroll 4
        for (int it = 0; it < NEXP; it++) {
            float v = w[it*HD + tid];
            float bhf = __uint_as_float(__float_as_uint(v) & 0xFFFFE000u);
            float res = (v - bhf) * 1024.0f;
            int k = tid;
            int h = k >> 4, j = k & 15, c = j >> 2, p = j & 3;
            int lane_t = (it & 7)*4 + c;
            int nt = it >> 3;
            int base = ((h*4 + nt)*32 + lane_t)*8;
            Bt[base + p]     = __float2half_rn(bhf);
            Bt[base + 4 + p] = __float2half_rn(res);
        }
    }
    if (tid < 2*NEXP) { s_aux[tid>>5][tid&31] = 0.0f; s_cnt[tid>>5][tid&31] = 0; }
    __syncthreads();

    char* Awarp = Aring + warp * (NSTAGE*STAGE_B);
    const uint32_t Abase = (uint32_t)__cvta_generic_to_shared(Awarp);
    const int cp_row = lane >> 2;
    const int cp_gr  = lane & 3;

    for (int tile = t_start + warp; tile < t_end; tile += WARPS) {
        const int tb = tile * TOK_PER_TILE;
        const int bi = (tile >> 8) - b_base;
        const float* xbase = hs + (size_t)tb * HD;

        // prologue: stage h-groups 0 and 1
        #pragma unroll
        for (int p = 0; p < NSTAGE; p++) {
            uint32_t dst = Abase + p*STAGE_B;
            #pragma unroll
            for (int it = 0; it < 4; it++) {
                int row = it*8 + cp_row;
                cp_async16(dst + row*64 + cp_gr*16,
                           xbase + (size_t)row*HD + p*16 + cp_gr*4);
            }
            cp_commit();
        }

        float acc0[2][4][4], acc1[2][4][4];
        #pragma unroll
        for (int mt = 0; mt < 2; mt++)
            #pragma unroll
            for (int nt = 0; nt < 4; nt++)
                #pragma unroll
                for (int i = 0; i < 4; i++) { acc0[mt][nt][i] = 0.0f; acc1[mt][nt][i] = 0.0f; }

        #pragma unroll
        for (int h = 0; h < NH; h++) {
            cp_wait<1>();
            const char* st = Awarp + (h & 1)*STAGE_B;

            // A fragment rows (conflict-free LDS.128); physical k-quad = lq
            float4 rA[4];
            rA[0] = *(const float4*)(st + (lr     )*64 + lq*16);
            rA[1] = *(const float4*)(st + (lr +  8)*64 + lq*16);
            rA[2] = *(const float4*)(st + (lr + 16)*64 + lq*16);
            rA[3] = *(const float4*)(st + (lr + 24)*64 + lq*16);

            // refill this slot with h-group h+2
            if (h + NSTAGE < NH) {
                uint32_t dst = Abase + (h & 1)*STAGE_B;
                #pragma unroll
                for (int it = 0; it < 4; it++) {
                    int row = it*8 + cp_row;
                    cp_async16(dst + row*64 + cp_gr*16,
                               xbase + (size_t)row*HD + (h+NSTAGE)*16 + cp_gr*4);
                }
            }
            cp_commit();

            // exact split: hi = mask13 (fp16-exact), lo = x - hi (unscaled)
            uint32_t ah[2][4], am[2][4];
            #pragma unroll
            for (int mt = 0; mt < 2; mt++) {
                #pragma unroll
                for (int rr = 0; rr < 2; rr++) {
                    float4 f = rA[mt*2 + rr];
                    float hx = __uint_as_float(__float_as_uint(f.x) & 0xFFFFE000u);
                    float hy = __uint_as_float(__float_as_uint(f.y) & 0xFFFFE000u);
                    float hz = __uint_as_float(__float_as_uint(f.z) & 0xFFFFE000u);
                    float hw = __uint_as_float(__float_as_uint(f.w) & 0xFFFFE000u);
                    ah[mt][0 + rr] = pk16(hx, hy);
                    ah[mt][2 + rr] = pk16(hz, hw);
                    am[mt][0 + rr] = pk16(f.x - hx, f.y - hy);
                    am[mt][2 + rr] = pk16(f.z - hz, f.w - hw);
                }
            }

            #pragma unroll
            for (int nt = 0; nt < 4; nt++) {
                uint4 bb = *(const uint4*)&Btab[((h*4 + nt)*32 + lane)*4];
                #pragma unroll
                for (int mt = 0; mt < 2; mt++) {
                    mma_f16(acc0[mt][nt], ah[mt][0], ah[mt][1], ah[mt][2], ah[mt][3], bb.x, bb.y);
                    mma_f16(acc0[mt][nt], am[mt][0], am[mt][1], am[mt][2], am[mt][3], bb.x, bb.y);
                    mma_f16(acc1[mt][nt], ah[mt][0], ah[mt][1], ah[mt][2], ah[mt][3], bb.z, bb.w);
                    mma_f16(acc1[mt][nt], am[mt][0], am[mt][1], am[mt][2], am[mt][3], bb.z, bb.w);
                }
            }
        }
        cp_wait<0>();

        // ---- epilogue: logit = acc0 + acc1/1024 ----
        float aux8[8];
        #pragma unroll
        for (int i = 0; i < 8; i++) aux8[i] = 0.0f;

        #pragma unroll
        for (int mt = 0; mt < 2; mt++) {
            #pragma unroll
            for (int half = 0; half < 2; half++) {
                float lg[8];
                #pragma unroll
                for (int nt = 0; nt < 4; nt++) {
                    lg[nt*2]   = acc0[mt][nt][half*2]   + acc1[mt][nt][half*2]   * 9.765625e-4f;
                    lg[nt*2+1] = acc0[mt][nt][half*2+1] + acc1[mt][nt][half*2+1] * 9.765625e-4f;
                }
                float m = lg[0]; int a = lq*2;
                #pragma unroll
                for (int i = 1; i < 8; i++) {
                    int e = (i>>1)*8 + lq*2 + (i&1);
                    if (lg[i] > m) { m = lg[i]; a = e; }
                }
                #pragma unroll
                for (int d = 1; d <= 2; d <<= 1) {
                    float om = __shfl_xor_sync(0xffffffffu, m, d);
                    int   oa = __shfl_xor_sync(0xffffffffu, a, d);
                    if (om > m || (om == m && oa < a)) { m = om; a = oa; }
                }
                float ex[8]; float s = 0.0f;
                #pragma unroll
                for (int i = 0; i < 8; i++) { ex[i] = __expf(lg[i] - m); s += ex[i]; }
                #pragma unroll
                for (int d = 1; d <= 2; d <<= 1) s += __shfl_xor_sync(0xffffffffu, s, d);
                float inv = 1.0f / s;
                #pragma unroll
                for (int i = 0; i < 8; i++) aux8[i] += ex[i] * inv;
                if (lq == 0) {
                    int gidx = tb + mt*16 + half*8 + lr;
                    out[gidx]            = (float)a;
                    out[N_TOKENS + gidx] = inv;
                    atomicAdd(&s_cnt[bi][a], 1);
                }
            }
        }

        #pragma unroll
        for (int i = 0; i < 8; i++) {
            float v = aux8[i];
            #pragma unroll
            for (int d = 4; d <= 16; d <<= 1) v += __shfl_xor_sync(0xffffffffu, v, d);
            if (lane < 4) atomicAdd(&s_aux[bi][(i>>1)*8 + lane*2 + (i&1)], v);
        }
    }
    __syncthreads();

    if (tid < 2*NEXP) {
        int r = tid >> 5, e = tid & 31;
        int br = b_base + r;
        if (br < BATCH) {
            atomicAdd(&g_ssum[br*NEXP + e], s_aux[r][e]);
            atomicAdd(&g_cnt [br*NEXP + e], s_cnt[r][e]);
        }
    }

    // ---- last block: finalize aux loss, reset globals ----
    if (tid == 0) {
        __threadfence();
        unsigned ticket = atomicAdd(&g_done, 1u);
        s_last = (ticket == (unsigned)(gridDim.x - 1));
    }
    __syncthreads();
    if (s_last) {
        __threadfence();
        __shared__ float red[TPB];
        float term = 0.0f;
        #pragma unroll
        for (int i = tid; i < BATCH*NEXP; i += TPB)
            term += ((float)g_cnt[i] * (1.0f/256.0f)) * (g_ssum[i] * (1.0f/(float)SEQ));
        red[tid] = term;
        __syncthreads();
        #pragma unroll
        for (int s2 = TPB/2; s2 > 0; s2 >>= 1) {
            if (tid < s2) red[tid] += red[tid + s2];
            __syncthreads();
        }
        if (tid == 0) out[2*N_TOKENS] = red[0] * (0.001f / (float)BATCH);
        #pragma unroll
        for (int i = tid; i < BATCH*NEXP; i += TPB) { g_ssum[i] = 0.0f; g_cnt[i] = 0; }
        if (tid == 0) g_done = 0u;
    }
}

extern "C" void kernel_launch(void* const* d_in, const int* in_sizes, int n_in,
                              void* d_out, int out_size) {
    const float* hs = (const float*)d_in[0];
    const float* w  = (const float*)d_in[1];
    float* out = (float*)d_out;
    cudaFuncSetAttribute(gate_kernel, cudaFuncAttributeMaxDynamicSharedMemorySize, SMEM_DYN);
    gate_kernel<<<NBLK, TPB, SMEM_DYN>>>(hs, w, out);
}